// round 11
// baseline (speedup 1.0000x reference)
#include <cuda_runtime.h>
#include <math.h>

#define NB   64
#define NC   512
#define NT   128
#define NV   1024
#define NQ   8
#define NIDX 255
#define NELEM (NB*NC*NT)
#define PLANE ((long long)NB*NT*NC)

// ---------------- device scratch ----------------
__device__ float g_zq[NELEM];
__device__ float g_zhat[NELEM];
__device__ float g_xd[NB*NC*NT];
__device__ float g_xs_a[2ll*NB*NT*NC];   // conv1 input tf32 splits [2][b][t][ci-permuted]
__device__ float g_xs_b[2ll*NB*NT*NC];   // conv2 input tf32 splits
__device__ float g_wsp[16ll*6*NC*NC];    // [qd][split*3+tap][co][ci-permuted]
__device__ float g_cnorm[NQ*NV];
__device__ unsigned long long g_bestkey[NB*NT];
__device__ int   g_idxbuf[NB*NIDX];
__device__ int   g_counts[NV];
__device__ float g_partial[256];
__device__ float g_sums[3];

// ---------------- helpers ----------------
__device__ __forceinline__ float tf32r(float x) {
    unsigned u;
    asm("cvt.rna.tf32.f32 %0, %1;" : "=r"(u) : "f"(x));
    return __uint_as_float(u);
}
__device__ __forceinline__ void split2(float x, float& hi, float& lo) {
    hi = tf32r(x);
    lo = tf32r(x - hi);
}
__device__ __forceinline__ int pos8(int c) {           // fragment-ready permutation
    return (c & ~7) | ((c & 3) << 1) | ((c >> 2) & 1);
}
__device__ __forceinline__ unsigned smem_u32(const void* p) {
    unsigned a;
    asm("{ .reg .u64 t; cvta.to.shared.u64 t, %1; cvt.u32.u64 %0, t; }" : "=r"(a) : "l"(p));
    return a;
}
__device__ __forceinline__ unsigned long long dup2(float x) {
    unsigned long long r;
    asm("mov.b64 %0, {%1, %1};" : "=l"(r) : "f"(x));
    return r;
}
__device__ __forceinline__ void fma2(unsigned long long& a, unsigned long long x, unsigned long long y) {
    asm("fma.rn.f32x2 %0, %1, %2, %0;" : "+l"(a) : "l"(x), "l"(y));
}
__device__ __forceinline__ float2 unpack2(unsigned long long v) {
    float2 f;
    asm("mov.b64 {%0, %1}, %2;" : "=f"(f.x), "=f"(f.y) : "l"(v));
    return f;
}
__device__ __forceinline__ void mma_tf32(float* d, const unsigned* a, uint2 b) {
    asm volatile(
        "mma.sync.aligned.m16n8k8.row.col.f32.tf32.tf32.f32 "
        "{%0,%1,%2,%3}, {%4,%5,%6,%7}, {%8,%9}, {%0,%1,%2,%3};"
        : "+f"(d[0]), "+f"(d[1]), "+f"(d[2]), "+f"(d[3])
        : "r"(a[0]), "r"(a[1]), "r"(a[2]), "r"(a[3]), "r"(b.x), "r"(b.y));
}

// ---------------- launch 0: init + cnorm + wsplit (fused) ----------------
__global__ void mega_init_kernel(const float* __restrict__ z, const float* __restrict__ cb,
                                 const float* __restrict__ pw) {
    int bx = blockIdx.x;
    int tid = threadIdx.x;
    if (bx < 2048) {
        long long stride = 2048ll * 256;
        long long t0 = (long long)bx * 256 + tid;
        for (long long i = t0; i < NELEM; i += stride) { g_zq[i] = z[i]; g_zhat[i] = 0.0f; }
        if (t0 < 3)   g_sums[t0] = 0.0f;
        if (t0 < NV)  g_counts[t0] = 0;
        if (t0 < 256) g_partial[t0] = 0.0f;
        if (t0 < NB*NT) g_bestkey[t0] = ~0ULL;
    } else if (bx < 2048 + 8192) {
        int row = bx - 2048;
        const float* p = cb + (long long)row * NC;
        float s = 0.0f;
        for (int c = tid; c < NC; c += 256) { float x = p[c]; s += x * x; }
        __shared__ float sh[8];
        for (int o = 16; o > 0; o >>= 1) s += __shfl_down_sync(0xffffffffu, s, o);
        if ((tid & 31) == 0) sh[tid >> 5] = s;
        __syncthreads();
        if (tid == 0) {
            float t = 0.0f;
            for (int w = 0; w < 8; w++) t += sh[w];
            g_cnorm[row] = t;
        }
    } else {
        long long i = (long long)(bx - 10240) * 256 + tid;
        if (i >= 16ll * NC * NC) return;
        int qd = (int)(i >> 18);
        int r  = (int)(i & (NC*NC - 1));
        int co = r >> 9, ci = r & 511;
        const float* src = pw + (((long long)qd * NC + co) * NC + ci) * 3;
        float* dst = g_wsp + (long long)qd * 6 * NC * NC;
        int cip = pos8(ci);
#pragma unroll
        for (int k = 0; k < 3; k++) {
            float hi, lo;
            split2(src[k], hi, lo);
            dst[(long long)k * NC * NC + co * NC + cip]       = hi;
            dst[(long long)(3 + k) * NC * NC + co * NC + cip] = lo;
        }
    }
}

// ---------------- launch 1: fully fused s=1 quantize ----------------
__global__ __launch_bounds__(256) void quant_s1_kernel(const float* __restrict__ cb) {
    __shared__ float xs[512];
    __shared__ unsigned long long wbest[8];
    int b = blockIdx.x;
    int tid = threadIdx.x;
    int wp = tid >> 5, lane = tid & 31;

    for (int i = 0; i < 64; i++) {
        int row = wp * 64 + i;
        float4 v = ((const float4*)(g_zq + (long long)(b * NC + row) * NT))[lane];
        float s = v.x + v.y + v.z + v.w;
        for (int o = 16; o > 0; o >>= 1) s += __shfl_xor_sync(0xffffffffu, s, o);
        if (lane == 0) xs[row] = s * (1.0f / 128.0f);
    }
    __syncthreads();

    float bestv = INFINITY;
    int besti = 0;
    for (int cc = 0; cc < 128; cc++) {
        int code = wp * 128 + cc;
        const float* cbr = cb + (long long)code * 512;
        float d = 0.0f;
#pragma unroll
        for (int e = 0; e < 16; e++) d += xs[lane + 32 * e] * cbr[lane + 32 * e];
        for (int o = 16; o > 0; o >>= 1) d += __shfl_xor_sync(0xffffffffu, d, o);
        float sc = g_cnorm[code] - 2.0f * d;
        if (sc < bestv) { bestv = sc; besti = code; }
    }
    if (lane == 0) {
        unsigned u = __float_as_uint(bestv);
        u = (u & 0x80000000u) ? ~u : (u | 0x80000000u);
        wbest[wp] = ((unsigned long long)u << 32) | (unsigned)besti;
    }
    __syncthreads();
    if (tid == 0) {
        unsigned long long k = wbest[0];
        for (int i = 1; i < 8; i++) if (wbest[i] < k) k = wbest[i];
        int idx = (int)(k & 0xFFFFFFFFULL);
        g_idxbuf[b * NIDX] = idx;
        atomicAdd(&g_counts[idx], 1);
    }
}

// ---------------- downsample ----------------
__global__ void downsample_warp_kernel(int s, int slog) {
    int r = NT >> slog;
    int i = blockIdx.x * 8 + (threadIdx.x >> 5);
    int lane = threadIdx.x & 31;
    if (i >= NB * NC * s) return;
    int j  = i & (s - 1);
    int bc = i >> slog;
    const float* src = g_zq + (long long)bc * NT + j * r;
    float acc;
    if (r == 64) { float2 v = ((const float2*)src)[lane]; acc = v.x + v.y; }
    else         { acc = src[lane]; }
    for (int o = 16; o > 0; o >>= 1) acc += __shfl_xor_sync(0xffffffffu, acc, o);
    if (lane == 0) g_xd[i] = acc * (1.0f / (float)r);
}
__global__ void downsample_kernel(int s, int slog) {
    int total = NB * NC * s;
    int r = NT >> slog;
    int i = blockIdx.x * blockDim.x + threadIdx.x;
    if (i >= total) return;
    int j  = i & (s - 1);
    int bc = i >> slog;
    const float* src = g_zq + (long long)bc * NT + j * r;
    float acc = 0.0f;
    for (int k = 0; k < r; k++) acc += src[k];
    g_xd[i] = acc * (1.0f / (float)r);
}

// ---------------- quantize (s in 2..8) ----------------
template<int S>
__global__ __launch_bounds__(256) void quantize_small_kernel(const float* __restrict__ cb, int q) {
    __shared__ float xs[S][512];
    int b  = blockIdx.x;
    int c0 = blockIdx.y * 128;
    int tid = threadIdx.x;
    for (int e = tid; e < S * 512; e += 256) {
        int j = e >> 9, ch = e & 511;
        xs[j][ch] = g_xd[(b * 512 + ch) * S + j];
    }
    __syncthreads();
    int w = tid >> 5, lane = tid & 31;
    float bestv[S]; int besti[S];
#pragma unroll
    for (int j = 0; j < S; j++) { bestv[j] = INFINITY; besti[j] = 0; }
    for (int cc = 0; cc < 16; cc++) {
        int code = c0 + w * 16 + cc;
        const float* cbr = cb + (long long)code * 512;
        float cv[16];
#pragma unroll
        for (int e = 0; e < 16; e++) cv[e] = cbr[lane + 32 * e];
        float cn = g_cnorm[q * NV + code];
#pragma unroll
        for (int j = 0; j < S; j++) {
            float d = 0.0f;
#pragma unroll
            for (int e = 0; e < 16; e++) d += xs[j][lane + 32 * e] * cv[e];
            for (int o = 16; o > 0; o >>= 1) d += __shfl_xor_sync(0xffffffffu, d, o);
            float sc = cn - 2.0f * d;
            if (sc < bestv[j]) { bestv[j] = sc; besti[j] = code; }
        }
    }
    if (lane == 0) {
#pragma unroll
        for (int j = 0; j < S; j++) {
            unsigned u = __float_as_uint(bestv[j]);
            u = (u & 0x80000000u) ? ~u : (u | 0x80000000u);
            atomicMin(&g_bestkey[b * S + j], ((unsigned long long)u << 32) | (unsigned)besti[j]);
        }
    }
}

// ---------------- quantize (s>=16) ----------------
__global__ __launch_bounds__(256) void quantize_gemm_kernel(
    const float* __restrict__ cb, int q, int s, int slog)
{
    const int m0 = blockIdx.x * 64;
    const int n0 = blockIdx.y * 128;
    __shared__ float As[32][65];
    __shared__ float Bs[32][130];
    const int tid = threadIdx.x;
    const int ti = tid >> 4, tj = tid & 15;
    unsigned long long acc[4][4];
#pragma unroll
    for (int r = 0; r < 4; r++)
#pragma unroll
        for (int c = 0; c < 4; c++) acc[r][c] = 0ULL;
    for (int kc = 0; kc < NC; kc += 32) {
#pragma unroll
        for (int it = 0; it < 8; it++) {
            int e = tid + 256 * it;
            int m = e & 63, kk = e >> 6;
            int gm = m0 + m;
            int b = gm >> slog, j = gm & (s - 1);
            As[kk][m] = g_xd[(((long long)b * NC + (kc + kk)) << slog) + j];
        }
#pragma unroll
        for (int it = 0; it < 16; it++) {
            int e = tid + 256 * it;
            int kk = e & 31, n = e >> 5;
            Bs[kk][n] = cb[(long long)(n0 + n) * NC + kc + kk];
        }
        __syncthreads();
#pragma unroll 8
        for (int kk = 0; kk < 32; kk++) {
            unsigned long long a2[4], b2[4];
#pragma unroll
            for (int r = 0; r < 4; r++) a2[r] = dup2(As[kk][ti + 16 * r]);
#pragma unroll
            for (int c = 0; c < 4; c++) b2[c] = *(const unsigned long long*)&Bs[kk][2 * tj + 32 * c];
#pragma unroll
            for (int r = 0; r < 4; r++)
#pragma unroll
                for (int c = 0; c < 4; c++) fma2(acc[r][c], a2[r], b2[c]);
        }
        __syncthreads();
    }
    float bestv[4]; int besti[4];
#pragma unroll
    for (int r = 0; r < 4; r++) { bestv[r] = INFINITY; besti[r] = 0; }
#pragma unroll
    for (int c = 0; c < 4; c++) {
        int n = n0 + 2 * tj + 32 * c;
        float cn0 = g_cnorm[q * NV + n], cn1 = g_cnorm[q * NV + n + 1];
#pragma unroll
        for (int r = 0; r < 4; r++) {
            float2 dv = unpack2(acc[r][c]);
            float s0 = cn0 - 2.0f * dv.x, s1 = cn1 - 2.0f * dv.y;
            if (s0 < bestv[r]) { bestv[r] = s0; besti[r] = n; }
            if (s1 < bestv[r]) { bestv[r] = s1; besti[r] = n + 1; }
        }
    }
#pragma unroll
    for (int r = 0; r < 4; r++) {
        float v = bestv[r]; int ix = besti[r];
        for (int off = 8; off > 0; off >>= 1) {
            float ov = __shfl_down_sync(0xffffffffu, v, off, 16);
            int   oi = __shfl_down_sync(0xffffffffu, ix, off, 16);
            if (ov < v || (ov == v && oi < ix)) { v = ov; ix = oi; }
        }
        if (tj == 0) {
            unsigned u = __float_as_uint(v);
            u = (u & 0x80000000u) ? ~u : (u | 0x80000000u);
            atomicMin(&g_bestkey[m0 + ti + 16 * r], ((unsigned long long)u << 32) | (unsigned)ix);
        }
    }
}

// ---------------- extract idx + histogram (s>=2) ----------------
__global__ void post_quantize_kernel(int s, int slog) {
    int m = blockIdx.x * blockDim.x + threadIdx.x;
    if (m >= NB * s) return;
    int v = (int)(g_bestkey[m] & 0xFFFFFFFFULL);
    int b = m >> slog, j = m & (s - 1);
    g_idxbuf[b * NIDX + (s - 1) + j] = v;
    atomicAdd(&g_counts[v], 1);
}

// ---------------- upsample -> tf32 splits (ci permuted) ----------------
__global__ void upsample_split_kernel(const float* __restrict__ cb, int s) {
    int b = blockIdx.x, t = blockIdx.y;
    float u = (t + 0.5f) * ((float)s / 128.0f) - 0.5f;
    float jf = floorf(u);
    float f = u - jf;
    int j0 = (int)jf, j1 = j0 + 1;
    if (j0 < 0) j0 = 0; if (j0 > s - 1) j0 = s - 1;
    if (j1 < 0) j1 = 0; if (j1 > s - 1) j1 = s - 1;
    int v0 = g_idxbuf[b * NIDX + (s - 1) + j0];
    int v1 = g_idxbuf[b * NIDX + (s - 1) + j1];
    const float* c0 = cb + (long long)v0 * NC;
    const float* c1 = cb + (long long)v1 * NC;
    float w1 = f, w0 = 1.0f - f;
    long long base = ((long long)(b * NT + t)) * NC;
    for (int c = threadIdx.x; c < NC; c += 128) {
        float val = w0 * c0[c] + w1 * c1[c];
        float hi, lo;
        split2(val, hi, lo);
        int cp = pos8(c);
        g_xs_a[base + cp]         = hi;
        g_xs_a[base + cp + PLANE] = lo;
    }
}

// ---------------- tf32 mma conv: 8-ci chunks, pitch 8 (conflict-free), 4-deep cp.async ----------------
// smem floats: W 4 bufs * 6*1024 @0; X 4 bufs * 4*1040 @24576. total 41216 fl = 164864 B.
#define WBUF 6144
#define XOFF 24576
#define XBUF 4160
#define CONV_SMEM (41216*4)
__global__ __launch_bounds__(512, 1) void conv_tc_kernel(
    const float* __restrict__ xs,   // [2][b][t][ci-permuted]
    const float* __restrict__ wsp,  // [6][co][ci-permuted] for this layer
    const float* __restrict__ bias,
    float* __restrict__ ys,
    const float* __restrict__ z, int fuse)
{
    extern __shared__ float sm[];
    const unsigned sbase = smem_u32(sm);
    const int tid = threadIdx.x, lane = tid & 31, wid = tid >> 5;
    const int h = wid >> 3, wh = wid & 7;
    const int cg = wh >> 2, tg = wh & 3;
    const int b0 = blockIdx.y * 2, co0 = blockIdx.x * 128;
    const int lq = lane >> 2, lr = lane & 3;

    // zero X halo rows (rows 0 and 129 of each (buf, plane)) once
    for (int e = tid; e < 256; e += 512) {
        int w = e & 7, r = e >> 3;             // r < 32
        int buf = r >> 3, pl = (r >> 1) & 3, rr = r & 1;
        sm[XOFF + buf * XBUF + pl * 1040 + (rr ? 129 : 0) * 8 + w] = 0.0f;
    }

    float acc[4][4][4];
#pragma unroll
    for (int mt = 0; mt < 4; mt++)
#pragma unroll
        for (int nt = 0; nt < 4; nt++)
#pragma unroll
            for (int r = 0; r < 4; r++) acc[mt][nt][r] = 0.0f;

    // ---- async copy issuers (chunk = 8 ci) ----
#define ISSUE_W(CI0, BUF) do { \
    _Pragma("unroll") \
    for (int i = 0; i < 3; i++) { \
        int e = tid + 512 * i; \
        int tile = e >> 8, r = e & 255, row = r >> 1, q = r & 1; \
        const float* src = wsp + (long long)tile * (NC * NC) \
                           + (long long)(co0 + row) * NC + (CI0) + q * 4; \
        unsigned dst = sbase + (unsigned)((BUF) * WBUF + tile * 1024 + row * 8 + q * 4) * 4u; \
        asm volatile("cp.async.cg.shared.global [%0], [%1], 16;" :: "r"(dst), "l"(src)); \
    } } while (0)
#define ISSUE_X(CI0, BUF) do { \
    _Pragma("unroll") \
    for (int i = 0; i < 2; i++) { \
        int e = tid + 512 * i; \
        int hb = e >> 9, sp = (e >> 8) & 1, r = e & 255, row = r >> 1, q = r & 1; \
        const float* src = xs + (long long)sp * PLANE \
                           + ((long long)((b0 + hb) * NT + row)) * NC + (CI0) + q * 4; \
        unsigned dst = sbase + (unsigned)(XOFF + (BUF) * XBUF + (hb * 2 + sp) * 1040 \
                                          + (row + 1) * 8 + q * 4) * 4u; \
        asm volatile("cp.async.cg.shared.global [%0], [%1], 16;" :: "r"(dst), "l"(src)); \
    } } while (0)

    // prologue: 3 chunks in flight
#pragma unroll
    for (int pc = 0; pc < 3; pc++) {
        ISSUE_W(pc * 8, pc);
        ISSUE_X(pc * 8, pc);
        asm volatile("cp.async.commit_group;");
    }

    for (int ch = 0; ch < 64; ch++) {
        const int buf = ch & 3;
        __syncthreads();                     // all warps done MMA(ch-1): its buffer is free
        if (ch + 3 < 64) {
            int ci1 = (ch + 3) * 8;
            ISSUE_W(ci1, (ch + 3) & 3);
            ISSUE_X(ci1, (ch + 3) & 3);
        }
        asm volatile("cp.async.commit_group;");
        asm volatile("cp.async.wait_group 3;");   // chunk ch has arrived

        const float* Wb = sm + buf * WBUF;
        const float* Xb = sm + XOFF + buf * XBUF + h * 2080;
#pragma unroll
        for (int tap = 0; tap < 3; tap++) {
            const float* Whi = Wb + tap * 1024;
            const float* Wlo = Wb + (3 + tap) * 1024;
            const float* Xhi = Xb;
            const float* Xlo = Xb + 1040;
            uint2 bhi[4], blo[4];
#pragma unroll
            for (int nt = 0; nt < 4; nt++) {
                int trow = tg * 32 + nt * 8 + lq + tap;
                bhi[nt] = *(const uint2*)&Xhi[trow * 8 + lr * 2];
                blo[nt] = *(const uint2*)&Xlo[trow * 8 + lr * 2];
            }
            unsigned ahi[4][4];
#pragma unroll
            for (int mt = 0; mt < 4; mt++) {
                int row = cg * 64 + mt * 16 + lq;
                uint2 p0 = *(const uint2*)&Whi[row * 8 + lr * 2];
                uint2 p1 = *(const uint2*)&Whi[(row + 8) * 8 + lr * 2];
                ahi[mt][0] = p0.x; ahi[mt][2] = p0.y;
                ahi[mt][1] = p1.x; ahi[mt][3] = p1.y;
            }
#pragma unroll
            for (int nt = 0; nt < 4; nt++)
#pragma unroll
                for (int mt = 0; mt < 4; mt++)
                    mma_tf32(acc[mt][nt], ahi[mt], bhi[nt]);
#pragma unroll
            for (int nt = 0; nt < 4; nt++)
#pragma unroll
                for (int mt = 0; mt < 4; mt++)
                    mma_tf32(acc[mt][nt], ahi[mt], blo[nt]);
            unsigned alo[4][4];
#pragma unroll
            for (int mt = 0; mt < 4; mt++) {
                int row = cg * 64 + mt * 16 + lq;
                uint2 p0 = *(const uint2*)&Wlo[row * 8 + lr * 2];
                uint2 p1 = *(const uint2*)&Wlo[(row + 8) * 8 + lr * 2];
                alo[mt][0] = p0.x; alo[mt][2] = p0.y;
                alo[mt][1] = p1.x; alo[mt][3] = p1.y;
            }
#pragma unroll
            for (int nt = 0; nt < 4; nt++)
#pragma unroll
                for (int mt = 0; mt < 4; mt++)
                    mma_tf32(acc[mt][nt], alo[mt], bhi[nt]);
        }
    }
#undef ISSUE_W
#undef ISSUE_X

    // ---- epilogue ----
    if (!fuse) {
        for (int hb = 0; hb < 2; hb++) {
            __syncthreads();
            if (h == hb) {
#pragma unroll
                for (int mt = 0; mt < 4; mt++)
#pragma unroll
                    for (int nt = 0; nt < 4; nt++) {
                        int row = cg * 64 + mt * 16 + lq;
                        int t0 = tg * 32 + nt * 8 + lr * 2;
                        sm[t0 * 130 + row]           = acc[mt][nt][0];
                        sm[(t0 + 1) * 130 + row]     = acc[mt][nt][1];
                        sm[t0 * 130 + row + 8]       = acc[mt][nt][2];
                        sm[(t0 + 1) * 130 + row + 8] = acc[mt][nt][3];
                    }
            }
            __syncthreads();
            int b = b0 + hb;
            for (int e = tid; e < 16384; e += 512) {
                int t = e >> 7, co = e & 127;
                float v = fmaxf(sm[t * 130 + co] + bias[co0 + co], 0.0f);
                float hi, lo;
                split2(v, hi, lo);
                long long o = ((long long)(b * NT + t)) * NC + co0 + pos8(co);
                ys[o]         = hi;
                ys[o + PLANE] = lo;
            }
        }
    } else {
        float lsum = 0.0f;
        int b = b0 + h;
#pragma unroll
        for (int mt = 0; mt < 4; mt++)
#pragma unroll
            for (int nt = 0; nt < 4; nt++) {
                int row = cg * 64 + mt * 16 + lq;
                int t0 = tg * 32 + nt * 8 + lr * 2;
#pragma unroll
                for (int hh = 0; hh < 2; hh++) {
                    int co = co0 + row + hh * 8;
                    float bv = bias[co];
                    float y0 = fmaxf(acc[mt][nt][hh * 2 + 0] + bv, 0.0f);
                    float y1 = fmaxf(acc[mt][nt][hh * 2 + 1] + bv, 0.0f);
                    long long i = ((long long)(b * NC + co)) * NT + t0;
                    float2 zh  = *(float2*)&g_zhat[i];
                    float2 zz  = *(const float2*)&z[i];
                    float2 zqv = *(float2*)&g_zq[i];
                    zh.x += y0; zh.y += y1;
                    *(float2*)&g_zhat[i] = zh;
                    zqv.x -= y0; zqv.y -= y1;
                    *(float2*)&g_zq[i] = zqv;
                    float d0 = zh.x - zz.x, d1 = zh.y - zz.y;
                    lsum += d0 * d0 + d1 * d1;
                }
            }
        __syncthreads();
        for (int o = 16; o > 0; o >>= 1) lsum += __shfl_down_sync(0xffffffffu, lsum, o);
        if ((tid & 31) == 0) sm[tid >> 5] = lsum;
        __syncthreads();
        if (tid == 0) {
            float s = 0.0f;
#pragma unroll
            for (int i2 = 0; i2 < 16; i2++) s += sm[i2];
            g_partial[blockIdx.y * 4 + blockIdx.x] = s;
        }
    }
}

// ---------------- per-scale finalize ----------------
__global__ void finalize_kernel(int s) {
    __shared__ float sh[32];
    int tid = threadIdx.x;
    float lsum = (tid < 128) ? g_partial[tid] : 0.0f;
    for (int o = 16; o > 0; o >>= 1) lsum += __shfl_down_sync(0xffffffffu, lsum, o);
    if ((tid & 31) == 0) sh[tid >> 5] = lsum;
    __syncthreads();
    float loss_total = 0.0f;
    if (tid == 0) for (int w = 0; w < 32; w++) loss_total += sh[w];
    __syncthreads();
    int c = g_counts[tid];
    float used = (c > 0) ? 1.0f : 0.0f;
    float p = (float)c / (float)(NB * s);
    float ent = p * logf(p + 1e-10f);
    float us = used;
    for (int o = 16; o > 0; o >>= 1) us += __shfl_down_sync(0xffffffffu, us, o);
    if ((tid & 31) == 0) sh[tid >> 5] = us;
    __syncthreads();
    float used_total = 0.0f;
    if (tid == 0) for (int w = 0; w < 32; w++) used_total += sh[w];
    __syncthreads();
    float es = ent;
    for (int o = 16; o > 0; o >>= 1) es += __shfl_down_sync(0xffffffffu, es, o);
    if ((tid & 31) == 0) sh[tid >> 5] = es;
    __syncthreads();
    float ent_total = 0.0f;
    if (tid == 0) for (int w = 0; w < 32; w++) ent_total += sh[w];
    if (tid == 0) {
        g_sums[0] += used_total * (100.0f / (float)NV);
        g_sums[1] += 1.25f * loss_total / (float)NELEM;
        g_sums[2] += expf(-ent_total);
    }
    g_counts[tid] = 0;
    for (int i = tid; i < NB * NT; i += 1024) g_bestkey[i] = ~0ULL;
}

// ---------------- write outputs ----------------
__global__ void writeout_kernel(float* __restrict__ out, int out_size) {
    long long stride = (long long)gridDim.x * blockDim.x;
    long long t0 = (long long)blockIdx.x * blockDim.x + threadIdx.x;
    for (long long i = t0; i < NELEM && i < out_size; i += stride) out[i] = g_zhat[i];
    if (t0 == 0) {
        if (NELEM + 0 < out_size) out[NELEM + 0] = g_sums[0] / 8.0f;
        if (NELEM + 1 < out_size) out[NELEM + 1] = g_sums[1] / 8.0f;
        if (NELEM + 2 < out_size) out[NELEM + 2] = g_sums[2] / 8.0f;
    }
    if (t0 < NB * NIDX && NELEM + 3 + t0 < out_size)
        out[NELEM + 3 + t0] = (float)g_idxbuf[t0];
}

// ---------------- host ----------------
extern "C" void kernel_launch(void* const* d_in, const int* in_sizes, int n_in,
                              void* d_out, int out_size) {
    const float* z  = (const float*)d_in[0];
    const float* cb = (const float*)d_in[1];
    const float* pw = (const float*)d_in[2];
    const float* pb = (const float*)d_in[3];
    float* out = (float*)d_out;

    void *p_xa = 0, *p_xb = 0, *p_w = 0;
    cudaGetSymbolAddress(&p_xa, g_xs_a);
    cudaGetSymbolAddress(&p_xb, g_xs_b);
    cudaGetSymbolAddress(&p_w,  g_wsp);
    cudaFuncSetAttribute(conv_tc_kernel, cudaFuncAttributeMaxDynamicSharedMemorySize, CONV_SMEM);

    mega_init_kernel<<<26624, 256>>>(z, cb, pw);                   // user launch 0

    for (int q = 0; q < NQ; q++) {
        int s = 1 << q, slog = q, M = NB * s;
        const float* cbq = cb + (long long)q * NV * NC;

        if (s == 1) {
            quant_s1_kernel<<<64, 256>>>(cbq);                     // launch 1
        } else if (s <= 4) {
            downsample_warp_kernel<<<(NB * NC * s) / 8, 256>>>(s, slog);
            if (s == 2) quantize_small_kernel<2><<<dim3(64, 8), 256>>>(cbq, q);
            else        quantize_small_kernel<4><<<dim3(64, 8), 256>>>(cbq, q);
            post_quantize_kernel<<<(M + 255) / 256, 256>>>(s, slog);
        } else {
            downsample_kernel<<<(NB * NC * s + 255) / 256, 256>>>(s, slog);
            if (s == 8) quantize_small_kernel<8><<<dim3(64, 8), 256>>>(cbq, q);
            else        quantize_gemm_kernel<<<dim3(M / 64, 8), 256>>>(cbq, q, s, slog);
            post_quantize_kernel<<<(M + 255) / 256, 256>>>(s, slog);
        }

        upsample_split_kernel<<<dim3(NB, NT), 128>>>(cbq, s);      // q=0: launch 2

        const float* w0 = (const float*)p_w + ((long long)q * 2 + 0) * 6 * NC * NC;
        const float* w1 = (const float*)p_w + ((long long)q * 2 + 1) * 6 * NC * NC;
        const float* b0 = pb + ((long long)q * 2 + 0) * NC;
        const float* b1 = pb + ((long long)q * 2 + 1) * NC;
        conv_tc_kernel<<<dim3(4, 32), 512, CONV_SMEM>>>(
            (const float*)p_xa, w0, b0, (float*)p_xb, z, 0);       // q=0: launch 3 <-- ncu -s 5
        conv_tc_kernel<<<dim3(4, 32), 512, CONV_SMEM>>>(
            (const float*)p_xb, w1, b1, (float*)0, z, 1);

        finalize_kernel<<<1, 1024>>>(s);
    }

    writeout_kernel<<<2048, 256>>>(out, out_size);
}

// round 12
// speedup vs baseline: 1.6173x; 1.6173x over previous
#include <cuda_runtime.h>
#include <cuda_fp16.h>
#include <math.h>

#define NB   64
#define NC   512
#define NT   128
#define NV   1024
#define NQ   8
#define NIDX 255
#define NELEM (NB*NC*NT)
#define PLANE ((long long)NB*NT*NC)

// ---------------- device scratch ----------------
__device__ float g_zq[NELEM];
__device__ float g_zhat[NELEM];
__device__ float g_xd[NB*NC*NT];
__device__ __align__(16) __half g_xs_a[2ll*NB*NT*NC];   // conv1 input fp16 splits [2][b][t][ci-perm16]
__device__ __align__(16) __half g_xs_b[2ll*NB*NT*NC];   // conv2 input fp16 splits
__device__ __align__(16) __half g_wsp[16ll*6*NC*NC];    // [qd][split*3+tap][co][ci-perm16]
__device__ float g_cnorm[NQ*NV];
__device__ unsigned long long g_bestkey[NB*NT];
__device__ int   g_idxbuf[NB*NIDX];
__device__ int   g_counts[NV];
__device__ float g_partial[256];
__device__ float g_sums[3];

// ---------------- helpers ----------------
__device__ __forceinline__ void split2h(float x, __half& h1, __half& h2) {
    h1 = __float2half_rn(x);
    h2 = __float2half_rn(x - __half2float(h1));
}
// within-16 channel permutation: c = 8a+2b+e -> 4b+2a+e (fragment-ready for k16 frags)
__device__ __forceinline__ int gpos16(int c) {
    return (c & ~15) | ((((c >> 1) & 3) << 2) | (((c >> 3) & 1) << 1) | (c & 1));
}
__device__ __forceinline__ unsigned smem_u32(const void* p) {
    unsigned a;
    asm("{ .reg .u64 t; cvta.to.shared.u64 t, %1; cvt.u32.u64 %0, t; }" : "=r"(a) : "l"(p));
    return a;
}
__device__ __forceinline__ unsigned long long dup2(float x) {
    unsigned long long r;
    asm("mov.b64 %0, {%1, %1};" : "=l"(r) : "f"(x));
    return r;
}
__device__ __forceinline__ void fma2(unsigned long long& a, unsigned long long x, unsigned long long y) {
    asm("fma.rn.f32x2 %0, %1, %2, %0;" : "+l"(a) : "l"(x), "l"(y));
}
__device__ __forceinline__ float2 unpack2(unsigned long long v) {
    float2 f;
    asm("mov.b64 {%0, %1}, %2;" : "=f"(f.x), "=f"(f.y) : "l"(v));
    return f;
}
__device__ __forceinline__ void mma_f16(float* d, const unsigned* a, uint2 b) {
    asm volatile(
        "mma.sync.aligned.m16n8k16.row.col.f32.f16.f16.f32 "
        "{%0,%1,%2,%3}, {%4,%5,%6,%7}, {%8,%9}, {%0,%1,%2,%3};"
        : "+f"(d[0]), "+f"(d[1]), "+f"(d[2]), "+f"(d[3])
        : "r"(a[0]), "r"(a[1]), "r"(a[2]), "r"(a[3]), "r"(b.x), "r"(b.y));
}

// ---------------- launch 0: init + cnorm + wsplit (fused) ----------------
__global__ void mega_init_kernel(const float* __restrict__ z, const float* __restrict__ cb,
                                 const float* __restrict__ pw) {
    int bx = blockIdx.x;
    int tid = threadIdx.x;
    if (bx < 2048) {
        long long stride = 2048ll * 256;
        long long t0 = (long long)bx * 256 + tid;
        for (long long i = t0; i < NELEM; i += stride) { g_zq[i] = z[i]; g_zhat[i] = 0.0f; }
        if (t0 < 3)   g_sums[t0] = 0.0f;
        if (t0 < NV)  g_counts[t0] = 0;
        if (t0 < 256) g_partial[t0] = 0.0f;
        if (t0 < NB*NT) g_bestkey[t0] = ~0ULL;
    } else if (bx < 2048 + 8192) {
        int row = bx - 2048;
        const float* p = cb + (long long)row * NC;
        float s = 0.0f;
        for (int c = tid; c < NC; c += 256) { float x = p[c]; s += x * x; }
        __shared__ float sh[8];
        for (int o = 16; o > 0; o >>= 1) s += __shfl_down_sync(0xffffffffu, s, o);
        if ((tid & 31) == 0) sh[tid >> 5] = s;
        __syncthreads();
        if (tid == 0) {
            float t = 0.0f;
            for (int w = 0; w < 8; w++) t += sh[w];
            g_cnorm[row] = t;
        }
    } else {
        long long i = (long long)(bx - 10240) * 256 + tid;
        if (i >= 16ll * NC * NC) return;
        int qd = (int)(i >> 18);
        int r  = (int)(i & (NC*NC - 1));
        int co = r >> 9, ci = r & 511;
        const float* src = pw + (((long long)qd * NC + co) * NC + ci) * 3;
        __half* dst = g_wsp + (long long)qd * 6 * NC * NC;
        int cip = gpos16(ci);
#pragma unroll
        for (int k = 0; k < 3; k++) {
            __half h1, h2;
            split2h(src[k], h1, h2);
            dst[(long long)k * NC * NC + co * NC + cip]       = h1;
            dst[(long long)(3 + k) * NC * NC + co * NC + cip] = h2;
        }
    }
}

// ---------------- launch 1: fully fused s=1 quantize ----------------
__global__ __launch_bounds__(256) void quant_s1_kernel(const float* __restrict__ cb) {
    __shared__ float xs[512];
    __shared__ unsigned long long wbest[8];
    int b = blockIdx.x;
    int tid = threadIdx.x;
    int wp = tid >> 5, lane = tid & 31;

    for (int i = 0; i < 64; i++) {
        int row = wp * 64 + i;
        float4 v = ((const float4*)(g_zq + (long long)(b * NC + row) * NT))[lane];
        float s = v.x + v.y + v.z + v.w;
        for (int o = 16; o > 0; o >>= 1) s += __shfl_xor_sync(0xffffffffu, s, o);
        if (lane == 0) xs[row] = s * (1.0f / 128.0f);
    }
    __syncthreads();

    float bestv = INFINITY;
    int besti = 0;
    for (int cc = 0; cc < 128; cc++) {
        int code = wp * 128 + cc;
        const float* cbr = cb + (long long)code * 512;
        float d = 0.0f;
#pragma unroll
        for (int e = 0; e < 16; e++) d += xs[lane + 32 * e] * cbr[lane + 32 * e];
        for (int o = 16; o > 0; o >>= 1) d += __shfl_xor_sync(0xffffffffu, d, o);
        float sc = g_cnorm[code] - 2.0f * d;
        if (sc < bestv) { bestv = sc; besti = code; }
    }
    if (lane == 0) {
        unsigned u = __float_as_uint(bestv);
        u = (u & 0x80000000u) ? ~u : (u | 0x80000000u);
        wbest[wp] = ((unsigned long long)u << 32) | (unsigned)besti;
    }
    __syncthreads();
    if (tid == 0) {
        unsigned long long k = wbest[0];
        for (int i = 1; i < 8; i++) if (wbest[i] < k) k = wbest[i];
        int idx = (int)(k & 0xFFFFFFFFULL);
        g_idxbuf[b * NIDX] = idx;
        atomicAdd(&g_counts[idx], 1);
    }
}

// ---------------- downsample ----------------
__global__ void downsample_warp_kernel(int s, int slog) {
    int r = NT >> slog;
    int i = blockIdx.x * 8 + (threadIdx.x >> 5);
    int lane = threadIdx.x & 31;
    if (i >= NB * NC * s) return;
    int j  = i & (s - 1);
    int bc = i >> slog;
    const float* src = g_zq + (long long)bc * NT + j * r;
    float acc;
    if (r == 64) { float2 v = ((const float2*)src)[lane]; acc = v.x + v.y; }
    else         { acc = src[lane]; }
    for (int o = 16; o > 0; o >>= 1) acc += __shfl_xor_sync(0xffffffffu, acc, o);
    if (lane == 0) g_xd[i] = acc * (1.0f / (float)r);
}
__global__ void downsample_kernel(int s, int slog) {
    int total = NB * NC * s;
    int r = NT >> slog;
    int i = blockIdx.x * blockDim.x + threadIdx.x;
    if (i >= total) return;
    int j  = i & (s - 1);
    int bc = i >> slog;
    const float* src = g_zq + (long long)bc * NT + j * r;
    float acc = 0.0f;
    for (int k = 0; k < r; k++) acc += src[k];
    g_xd[i] = acc * (1.0f / (float)r);
}

// ---------------- quantize (s in 2..8) ----------------
template<int S>
__global__ __launch_bounds__(256) void quantize_small_kernel(const float* __restrict__ cb, int q) {
    __shared__ float xs[S][512];
    int b  = blockIdx.x;
    int c0 = blockIdx.y * 128;
    int tid = threadIdx.x;
    for (int e = tid; e < S * 512; e += 256) {
        int j = e >> 9, ch = e & 511;
        xs[j][ch] = g_xd[(b * 512 + ch) * S + j];
    }
    __syncthreads();
    int w = tid >> 5, lane = tid & 31;
    float bestv[S]; int besti[S];
#pragma unroll
    for (int j = 0; j < S; j++) { bestv[j] = INFINITY; besti[j] = 0; }
    for (int cc = 0; cc < 16; cc++) {
        int code = c0 + w * 16 + cc;
        const float* cbr = cb + (long long)code * 512;
        float cv[16];
#pragma unroll
        for (int e = 0; e < 16; e++) cv[e] = cbr[lane + 32 * e];
        float cn = g_cnorm[q * NV + code];
#pragma unroll
        for (int j = 0; j < S; j++) {
            float d = 0.0f;
#pragma unroll
            for (int e = 0; e < 16; e++) d += xs[j][lane + 32 * e] * cv[e];
            for (int o = 16; o > 0; o >>= 1) d += __shfl_xor_sync(0xffffffffu, d, o);
            float sc = cn - 2.0f * d;
            if (sc < bestv[j]) { bestv[j] = sc; besti[j] = code; }
        }
    }
    if (lane == 0) {
#pragma unroll
        for (int j = 0; j < S; j++) {
            unsigned u = __float_as_uint(bestv[j]);
            u = (u & 0x80000000u) ? ~u : (u | 0x80000000u);
            atomicMin(&g_bestkey[b * S + j], ((unsigned long long)u << 32) | (unsigned)besti[j]);
        }
    }
}

// ---------------- quantize (s>=16) ----------------
__global__ __launch_bounds__(256) void quantize_gemm_kernel(
    const float* __restrict__ cb, int q, int s, int slog)
{
    const int m0 = blockIdx.x * 64;
    const int n0 = blockIdx.y * 128;
    __shared__ float As[32][65];
    __shared__ float Bs[32][130];
    const int tid = threadIdx.x;
    const int ti = tid >> 4, tj = tid & 15;
    unsigned long long acc[4][4];
#pragma unroll
    for (int r = 0; r < 4; r++)
#pragma unroll
        for (int c = 0; c < 4; c++) acc[r][c] = 0ULL;
    for (int kc = 0; kc < NC; kc += 32) {
#pragma unroll
        for (int it = 0; it < 8; it++) {
            int e = tid + 256 * it;
            int m = e & 63, kk = e >> 6;
            int gm = m0 + m;
            int b = gm >> slog, j = gm & (s - 1);
            As[kk][m] = g_xd[(((long long)b * NC + (kc + kk)) << slog) + j];
        }
#pragma unroll
        for (int it = 0; it < 16; it++) {
            int e = tid + 256 * it;
            int kk = e & 31, n = e >> 5;
            Bs[kk][n] = cb[(long long)(n0 + n) * NC + kc + kk];
        }
        __syncthreads();
#pragma unroll 8
        for (int kk = 0; kk < 32; kk++) {
            unsigned long long a2[4], b2[4];
#pragma unroll
            for (int r = 0; r < 4; r++) a2[r] = dup2(As[kk][ti + 16 * r]);
#pragma unroll
            for (int c = 0; c < 4; c++) b2[c] = *(const unsigned long long*)&Bs[kk][2 * tj + 32 * c];
#pragma unroll
            for (int r = 0; r < 4; r++)
#pragma unroll
                for (int c = 0; c < 4; c++) fma2(acc[r][c], a2[r], b2[c]);
        }
        __syncthreads();
    }
    float bestv[4]; int besti[4];
#pragma unroll
    for (int r = 0; r < 4; r++) { bestv[r] = INFINITY; besti[r] = 0; }
#pragma unroll
    for (int c = 0; c < 4; c++) {
        int n = n0 + 2 * tj + 32 * c;
        float cn0 = g_cnorm[q * NV + n], cn1 = g_cnorm[q * NV + n + 1];
#pragma unroll
        for (int r = 0; r < 4; r++) {
            float2 dv = unpack2(acc[r][c]);
            float s0 = cn0 - 2.0f * dv.x, s1 = cn1 - 2.0f * dv.y;
            if (s0 < bestv[r]) { bestv[r] = s0; besti[r] = n; }
            if (s1 < bestv[r]) { bestv[r] = s1; besti[r] = n + 1; }
        }
    }
#pragma unroll
    for (int r = 0; r < 4; r++) {
        float v = bestv[r]; int ix = besti[r];
        for (int off = 8; off > 0; off >>= 1) {
            float ov = __shfl_down_sync(0xffffffffu, v, off, 16);
            int   oi = __shfl_down_sync(0xffffffffu, ix, off, 16);
            if (ov < v || (ov == v && oi < ix)) { v = ov; ix = oi; }
        }
        if (tj == 0) {
            unsigned u = __float_as_uint(v);
            u = (u & 0x80000000u) ? ~u : (u | 0x80000000u);
            atomicMin(&g_bestkey[m0 + ti + 16 * r], ((unsigned long long)u << 32) | (unsigned)ix);
        }
    }
}

// ---------------- extract idx + histogram (s>=2) ----------------
__global__ void post_quantize_kernel(int s, int slog) {
    int m = blockIdx.x * blockDim.x + threadIdx.x;
    if (m >= NB * s) return;
    int v = (int)(g_bestkey[m] & 0xFFFFFFFFULL);
    int b = m >> slog, j = m & (s - 1);
    g_idxbuf[b * NIDX + (s - 1) + j] = v;
    atomicAdd(&g_counts[v], 1);
}

// ---------------- upsample -> fp16 splits (ci perm16) ----------------
__global__ void upsample_split_kernel(const float* __restrict__ cb, int s) {
    int b = blockIdx.x, t = blockIdx.y;
    float u = (t + 0.5f) * ((float)s / 128.0f) - 0.5f;
    float jf = floorf(u);
    float f = u - jf;
    int j0 = (int)jf, j1 = j0 + 1;
    if (j0 < 0) j0 = 0; if (j0 > s - 1) j0 = s - 1;
    if (j1 < 0) j1 = 0; if (j1 > s - 1) j1 = s - 1;
    int v0 = g_idxbuf[b * NIDX + (s - 1) + j0];
    int v1 = g_idxbuf[b * NIDX + (s - 1) + j1];
    const float* c0 = cb + (long long)v0 * NC;
    const float* c1 = cb + (long long)v1 * NC;
    float w1 = f, w0 = 1.0f - f;
    long long base = ((long long)(b * NT + t)) * NC;
    for (int c = threadIdx.x; c < NC; c += 128) {
        float val = w0 * c0[c] + w1 * c1[c];
        __half h1, h2;
        split2h(val, h1, h2);
        int cp = gpos16(c);
        g_xs_a[base + cp]         = h1;
        g_xs_a[base + cp + PLANE] = h2;
    }
}

// ---------------- fp16 mma conv: m16n8k16, 16-ci chunks, 2-deep cp.async, hoisted addressing ----------------
// smem bytes: W 2 bufs * 24576 @0; X 2 bufs * 16640 @49152. total 82432 B.
#define WBUF_B 24576
#define XOFF_B 49152
#define XBUF_B 16640
#define CONV_SMEM (XOFF_B + 2*XBUF_B)
__global__ __launch_bounds__(512, 1) void conv_tc_kernel(
    const __half* __restrict__ xs,   // [2][b][t][ci-perm16]
    const __half* __restrict__ wsp,  // [6][co][ci-perm16] for this layer
    const float* __restrict__ bias,
    __half* __restrict__ ys,
    const float* __restrict__ z, int fuse)
{
    extern __shared__ char smc[];
    float* smf = (float*)smc;
    const unsigned sbase = smem_u32(smc);
    const int tid = threadIdx.x, lane = tid & 31, wid = tid >> 5;
    const int h = wid >> 3, wh = wid & 7;
    const int cg = wh >> 2, tg = wh & 3;
    const int b0 = blockIdx.y * 2, co0 = blockIdx.x * 128;
    const int lq = lane >> 2, lr = lane & 3;

    // zero X halo rows (rows 0 and 129 of each (buf, plane)): 2*4*2*8 = 128 words
    for (int e = tid; e < 128; e += 512) {
        int word = e & 7, row2 = (e >> 3) & 1, pl = (e >> 4) & 3, buf = e >> 6;
        *(unsigned*)(smc + XOFF_B + buf * XBUF_B + pl * 4160 + (row2 ? 129 : 0) * 32 + word * 4) = 0u;
    }

    float acc[4][4][4];
#pragma unroll
    for (int mt = 0; mt < 4; mt++)
#pragma unroll
        for (int nt = 0; nt < 4; nt++)
#pragma unroll
            for (int r = 0; r < 4; r++) acc[mt][nt][r] = 0.0f;

    // ---- hoisted cp.async addressing ----
    const char* wsrc[3]; unsigned wdst[3];
#pragma unroll
    for (int i = 0; i < 3; i++) {
        int e = tid + 512 * i;             // < 1536 quads (6 tiles * 128 rows * 2)
        int tile = e >> 8, r = e & 255, row = r >> 1, q = r & 1;
        wsrc[i] = (const char*)(wsp + (long long)tile * (NC * NC)
                                + (long long)(co0 + row) * NC) + q * 16;
        wdst[i] = sbase + (unsigned)(tile * 4096 + row * 32 + q * 16);
    }
    const char* xsrc[2]; unsigned xdst[2];
#pragma unroll
    for (int i = 0; i < 2; i++) {
        int e = tid + 512 * i;             // < 1024 quads (4 planes * 128 rows * 2)
        int hbsp = e >> 8, r = e & 255, row = r >> 1, q = r & 1;
        int hb = hbsp >> 1, sp = hbsp & 1;
        xsrc[i] = (const char*)(xs + (long long)sp * PLANE
                                + ((long long)((b0 + hb) * NT + row)) * NC) + q * 16;
        xdst[i] = sbase + (unsigned)(XOFF_B + hbsp * 4160 + (row + 1) * 32 + q * 16);
    }
    int wdel = WBUF_B, xdel = XBUF_B;

#define ISSUE_ALL() do { \
    _Pragma("unroll") \
    for (int i = 0; i < 3; i++) { \
        asm volatile("cp.async.cg.shared.global [%0], [%1], 16;" :: "r"(wdst[i]), "l"(wsrc[i])); \
        wsrc[i] += 32; wdst[i] += wdel; \
    } \
    _Pragma("unroll") \
    for (int i = 0; i < 2; i++) { \
        asm volatile("cp.async.cg.shared.global [%0], [%1], 16;" :: "r"(xdst[i]), "l"(xsrc[i])); \
        xsrc[i] += 32; xdst[i] += xdel; \
    } \
    wdel = -wdel; xdel = -xdel; \
} while (0)

    ISSUE_ALL();                                   // chunk 0 -> buf 0
    asm volatile("cp.async.commit_group;");

    for (int ch = 0; ch < 32; ch++) {
        const int buf = ch & 1;
        asm volatile("cp.async.wait_group 0;");
        __syncthreads();                           // data(ch) visible; MMA(ch-1) done

        if (ch < 31) ISSUE_ALL();                  // chunk ch+1 -> other buffer
        asm volatile("cp.async.commit_group;");

        const char* Wb = smc + buf * WBUF_B;
        const char* Xw = smc + XOFF_B + buf * XBUF_B + h * 8320;  // this warp's batch planes
#pragma unroll
        for (int tap = 0; tap < 3; tap++) {
            const char* Whi = Wb + tap * 4096;
            const char* Wlo = Wb + (3 + tap) * 4096;
            uint2 bhi[4], blo[4];
#pragma unroll
            for (int nt = 0; nt < 4; nt++) {
                int trow = tg * 32 + nt * 8 + lq + tap;
                bhi[nt] = *(const uint2*)(Xw + trow * 32 + lr * 8);
                blo[nt] = *(const uint2*)(Xw + 4160 + trow * 32 + lr * 8);
            }
            unsigned a[4][4];
#pragma unroll
            for (int mt = 0; mt < 4; mt++) {
                int row = cg * 64 + mt * 16 + lq;
                uint2 p0 = *(const uint2*)(Whi + row * 32 + lr * 8);
                uint2 p1 = *(const uint2*)(Whi + (row + 8) * 32 + lr * 8);
                a[mt][0] = p0.x; a[mt][1] = p1.x; a[mt][2] = p0.y; a[mt][3] = p1.y;
            }
#pragma unroll
            for (int nt = 0; nt < 4; nt++)
#pragma unroll
                for (int mt = 0; mt < 4; mt++)
                    mma_f16(acc[mt][nt], a[mt], bhi[nt]);
#pragma unroll
            for (int nt = 0; nt < 4; nt++)
#pragma unroll
                for (int mt = 0; mt < 4; mt++)
                    mma_f16(acc[mt][nt], a[mt], blo[nt]);
#pragma unroll
            for (int mt = 0; mt < 4; mt++) {
                int row = cg * 64 + mt * 16 + lq;
                uint2 p0 = *(const uint2*)(Wlo + row * 32 + lr * 8);
                uint2 p1 = *(const uint2*)(Wlo + (row + 8) * 32 + lr * 8);
                a[mt][0] = p0.x; a[mt][1] = p1.x; a[mt][2] = p0.y; a[mt][3] = p1.y;
            }
#pragma unroll
            for (int nt = 0; nt < 4; nt++)
#pragma unroll
                for (int mt = 0; mt < 4; mt++)
                    mma_f16(acc[mt][nt], a[mt], bhi[nt]);
        }
    }
#undef ISSUE_ALL

    // ---- epilogue ----
    if (!fuse) {
        for (int hb = 0; hb < 2; hb++) {
            __syncthreads();
            if (h == hb) {
#pragma unroll
                for (int mt = 0; mt < 4; mt++)
#pragma unroll
                    for (int nt = 0; nt < 4; nt++) {
                        int row = cg * 64 + mt * 16 + lq;
                        int t0 = tg * 32 + nt * 8 + lr * 2;
                        smf[t0 * 130 + row]           = acc[mt][nt][0];
                        smf[(t0 + 1) * 130 + row]     = acc[mt][nt][1];
                        smf[t0 * 130 + row + 8]       = acc[mt][nt][2];
                        smf[(t0 + 1) * 130 + row + 8] = acc[mt][nt][3];
                    }
            }
            __syncthreads();
            int b = b0 + hb;
            for (int e = tid; e < 16384; e += 512) {
                int t = e >> 7, co = e & 127;
                float v = fmaxf(smf[t * 130 + co] + bias[co0 + co], 0.0f);
                __half h1, h2;
                split2h(v, h1, h2);
                int c = co0 + co;
                long long o = ((long long)(b * NT + t)) * NC + gpos16(c);
                ys[o]         = h1;
                ys[o + PLANE] = h2;
            }
        }
    } else {
        float lsum = 0.0f;
        int b = b0 + h;
#pragma unroll
        for (int mt = 0; mt < 4; mt++)
#pragma unroll
            for (int nt = 0; nt < 4; nt++) {
                int row = cg * 64 + mt * 16 + lq;
                int t0 = tg * 32 + nt * 8 + lr * 2;
#pragma unroll
                for (int hh = 0; hh < 2; hh++) {
                    int co = co0 + row + hh * 8;
                    float bv = bias[co];
                    float y0 = fmaxf(acc[mt][nt][hh * 2 + 0] + bv, 0.0f);
                    float y1 = fmaxf(acc[mt][nt][hh * 2 + 1] + bv, 0.0f);
                    long long i = ((long long)(b * NC + co)) * NT + t0;
                    float2 zh  = *(float2*)&g_zhat[i];
                    float2 zz  = *(const float2*)&z[i];
                    float2 zqv = *(float2*)&g_zq[i];
                    zh.x += y0; zh.y += y1;
                    *(float2*)&g_zhat[i] = zh;
                    zqv.x -= y0; zqv.y -= y1;
                    *(float2*)&g_zq[i] = zqv;
                    float d0 = zh.x - zz.x, d1 = zh.y - zz.y;
                    lsum += d0 * d0 + d1 * d1;
                }
            }
        __syncthreads();
        for (int o = 16; o > 0; o >>= 1) lsum += __shfl_down_sync(0xffffffffu, lsum, o);
        if ((tid & 31) == 0) smf[tid >> 5] = lsum;
        __syncthreads();
        if (tid == 0) {
            float s = 0.0f;
#pragma unroll
            for (int i2 = 0; i2 < 16; i2++) s += smf[i2];
            g_partial[blockIdx.y * 4 + blockIdx.x] = s;
        }
    }
}

// ---------------- per-scale finalize ----------------
__global__ void finalize_kernel(int s) {
    __shared__ float sh[32];
    int tid = threadIdx.x;
    float lsum = (tid < 128) ? g_partial[tid] : 0.0f;
    for (int o = 16; o > 0; o >>= 1) lsum += __shfl_down_sync(0xffffffffu, lsum, o);
    if ((tid & 31) == 0) sh[tid >> 5] = lsum;
    __syncthreads();
    float loss_total = 0.0f;
    if (tid == 0) for (int w = 0; w < 32; w++) loss_total += sh[w];
    __syncthreads();
    int c = g_counts[tid];
    float used = (c > 0) ? 1.0f : 0.0f;
    float p = (float)c / (float)(NB * s);
    float ent = p * logf(p + 1e-10f);
    float us = used;
    for (int o = 16; o > 0; o >>= 1) us += __shfl_down_sync(0xffffffffu, us, o);
    if ((tid & 31) == 0) sh[tid >> 5] = us;
    __syncthreads();
    float used_total = 0.0f;
    if (tid == 0) for (int w = 0; w < 32; w++) used_total += sh[w];
    __syncthreads();
    float es = ent;
    for (int o = 16; o > 0; o >>= 1) es += __shfl_down_sync(0xffffffffu, es, o);
    if ((tid & 31) == 0) sh[tid >> 5] = es;
    __syncthreads();
    float ent_total = 0.0f;
    if (tid == 0) for (int w = 0; w < 32; w++) ent_total += sh[w];
    if (tid == 0) {
        g_sums[0] += used_total * (100.0f / (float)NV);
        g_sums[1] += 1.25f * loss_total / (float)NELEM;
        g_sums[2] += expf(-ent_total);
    }
    g_counts[tid] = 0;
    for (int i = tid; i < NB * NT; i += 1024) g_bestkey[i] = ~0ULL;
}

// ---------------- write outputs ----------------
__global__ void writeout_kernel(float* __restrict__ out, int out_size) {
    long long stride = (long long)gridDim.x * blockDim.x;
    long long t0 = (long long)blockIdx.x * blockDim.x + threadIdx.x;
    for (long long i = t0; i < NELEM && i < out_size; i += stride) out[i] = g_zhat[i];
    if (t0 == 0) {
        if (NELEM + 0 < out_size) out[NELEM + 0] = g_sums[0] / 8.0f;
        if (NELEM + 1 < out_size) out[NELEM + 1] = g_sums[1] / 8.0f;
        if (NELEM + 2 < out_size) out[NELEM + 2] = g_sums[2] / 8.0f;
    }
    if (t0 < NB * NIDX && NELEM + 3 + t0 < out_size)
        out[NELEM + 3 + t0] = (float)g_idxbuf[t0];
}

// ---------------- host ----------------
extern "C" void kernel_launch(void* const* d_in, const int* in_sizes, int n_in,
                              void* d_out, int out_size) {
    const float* z  = (const float*)d_in[0];
    const float* cb = (const float*)d_in[1];
    const float* pw = (const float*)d_in[2];
    const float* pb = (const float*)d_in[3];
    float* out = (float*)d_out;

    void *p_xa = 0, *p_xb = 0, *p_w = 0;
    cudaGetSymbolAddress(&p_xa, g_xs_a);
    cudaGetSymbolAddress(&p_xb, g_xs_b);
    cudaGetSymbolAddress(&p_w,  g_wsp);
    cudaFuncSetAttribute(conv_tc_kernel, cudaFuncAttributeMaxDynamicSharedMemorySize, CONV_SMEM);

    mega_init_kernel<<<26624, 256>>>(z, cb, pw);                   // user launch 0

    for (int q = 0; q < NQ; q++) {
        int s = 1 << q, slog = q, M = NB * s;
        const float* cbq = cb + (long long)q * NV * NC;

        if (s == 1) {
            quant_s1_kernel<<<64, 256>>>(cbq);                     // launch 1
        } else if (s <= 4) {
            downsample_warp_kernel<<<(NB * NC * s) / 8, 256>>>(s, slog);
            if (s == 2) quantize_small_kernel<2><<<dim3(64, 8), 256>>>(cbq, q);
            else        quantize_small_kernel<4><<<dim3(64, 8), 256>>>(cbq, q);
            post_quantize_kernel<<<(M + 255) / 256, 256>>>(s, slog);
        } else {
            downsample_kernel<<<(NB * NC * s + 255) / 256, 256>>>(s, slog);
            if (s == 8) quantize_small_kernel<8><<<dim3(64, 8), 256>>>(cbq, q);
            else        quantize_gemm_kernel<<<dim3(M / 64, 8), 256>>>(cbq, q, s, slog);
            post_quantize_kernel<<<(M + 255) / 256, 256>>>(s, slog);
        }

        upsample_split_kernel<<<dim3(NB, NT), 128>>>(cbq, s);      // q=0: launch 2

        const __half* w0 = (const __half*)p_w + ((long long)q * 2 + 0) * 6 * NC * NC;
        const __half* w1 = (const __half*)p_w + ((long long)q * 2 + 1) * 6 * NC * NC;
        const float* b0 = pb + ((long long)q * 2 + 0) * NC;
        const float* b1 = pb + ((long long)q * 2 + 1) * NC;
        conv_tc_kernel<<<dim3(4, 32), 512, CONV_SMEM>>>(
            (const __half*)p_xa, w0, b0, (__half*)p_xb, z, 0);     // q=0: launch 3 <-- ncu -s 5
        conv_tc_kernel<<<dim3(4, 32), 512, CONV_SMEM>>>(
            (const __half*)p_xb, w1, b1, (__half*)0, z, 1);

        finalize_kernel<<<1, 1024>>>(s);
    }

    writeout_kernel<<<2048, 256>>>(out, out_size);
}

// round 13
// speedup vs baseline: 1.7702x; 1.0946x over previous
#include <cuda_runtime.h>
#include <cuda_fp16.h>
#include <math.h>

#define NB   64
#define NC   512
#define NT   128
#define NV   1024
#define NQ   8
#define NIDX 255
#define NELEM (NB*NC*NT)
#define PLANE ((long long)NB*NT*NC)
#define XDPLANE (8192ll*512)        // xd split plane (max M=8192 rows)
#define CBPLANE (8ll*NV*NC)         // codebook split plane

// ---------------- device scratch ----------------
__device__ float g_zq[NELEM];
__device__ float g_zhat[NELEM];
__device__ float g_xd[NB*NC*NT];
__device__ __align__(16) __half g_xs_a[2ll*NB*NT*NC];   // conv1 input fp16 splits [2][b][t][ci-perm16]
__device__ __align__(16) __half g_xs_b[2ll*NB*NT*NC];   // conv2 input fp16 splits
__device__ __align__(16) __half g_wsp[16ll*6*NC*NC];    // [qd][split*3+tap][co][ci-perm16]
__device__ __align__(16) __half g_xdh[2ll*8192*512];    // xd fp16 splits [2][m][ci-perm16]
__device__ __align__(16) __half g_cbh[2ll*8*NV*NC];     // codebook fp16 splits [2][q*NV+v][ci-perm16]
__device__ float g_cnorm[NQ*NV];
__device__ unsigned long long g_bestkey[NB*NT];
__device__ int   g_idxbuf[NB*NIDX];
__device__ int   g_counts[NV];
__device__ float g_partial[256];
__device__ float g_sums[3];

// ---------------- helpers ----------------
__device__ __forceinline__ void split2h(float x, __half& h1, __half& h2) {
    h1 = __float2half_rn(x);
    h2 = __float2half_rn(x - __half2float(h1));
}
// within-16 channel permutation (fragment-ready for k16 frags)
__device__ __forceinline__ int gpos16(int c) {
    return (c & ~15) | ((((c >> 1) & 3) << 2) | (((c >> 3) & 1) << 1) | (c & 1));
}
__device__ __forceinline__ unsigned smem_u32(const void* p) {
    unsigned a;
    asm("{ .reg .u64 t; cvta.to.shared.u64 t, %1; cvt.u32.u64 %0, t; }" : "=r"(a) : "l"(p));
    return a;
}
__device__ __forceinline__ void mma_f16(float* d, const unsigned* a, uint2 b) {
    asm volatile(
        "mma.sync.aligned.m16n8k16.row.col.f32.f16.f16.f32 "
        "{%0,%1,%2,%3}, {%4,%5,%6,%7}, {%8,%9}, {%0,%1,%2,%3};"
        : "+f"(d[0]), "+f"(d[1]), "+f"(d[2]), "+f"(d[3])
        : "r"(a[0]), "r"(a[1]), "r"(a[2]), "r"(a[3]), "r"(b.x), "r"(b.y));
}

// ---------------- launch 0: init + cnorm + wsplit + cbsplit (fused) ----------------
__global__ void mega_init_kernel(const float* __restrict__ z, const float* __restrict__ cb,
                                 const float* __restrict__ pw) {
    int bx = blockIdx.x;
    int tid = threadIdx.x;
    if (bx < 2048) {
        long long stride = 2048ll * 256;
        long long t0 = (long long)bx * 256 + tid;
        for (long long i = t0; i < NELEM; i += stride) { g_zq[i] = z[i]; g_zhat[i] = 0.0f; }
        if (t0 < 3)   g_sums[t0] = 0.0f;
        if (t0 < NV)  g_counts[t0] = 0;
        if (t0 < 256) g_partial[t0] = 0.0f;
        if (t0 < NB*NT) g_bestkey[t0] = ~0ULL;
    } else if (bx < 2048 + 8192) {
        int row = bx - 2048;
        const float* p = cb + (long long)row * NC;
        float s = 0.0f;
        for (int c = tid; c < NC; c += 256) { float x = p[c]; s += x * x; }
        __shared__ float sh[8];
        for (int o = 16; o > 0; o >>= 1) s += __shfl_down_sync(0xffffffffu, s, o);
        if ((tid & 31) == 0) sh[tid >> 5] = s;
        __syncthreads();
        if (tid == 0) {
            float t = 0.0f;
            for (int w = 0; w < 8; w++) t += sh[w];
            g_cnorm[row] = t;
        }
    } else if (bx < 2048 + 8192 + 16384) {
        long long i = (long long)(bx - 10240) * 256 + tid;
        if (i >= 16ll * NC * NC) return;
        int qd = (int)(i >> 18);
        int r  = (int)(i & (NC*NC - 1));
        int co = r >> 9, ci = r & 511;
        const float* src = pw + (((long long)qd * NC + co) * NC + ci) * 3;
        __half* dst = g_wsp + (long long)qd * 6 * NC * NC;
        int cip = gpos16(ci);
#pragma unroll
        for (int k = 0; k < 3; k++) {
            __half h1, h2;
            split2h(src[k], h1, h2);
            dst[(long long)k * NC * NC + co * NC + cip]       = h1;
            dst[(long long)(3 + k) * NC * NC + co * NC + cip] = h2;
        }
    } else {
        long long i = (long long)(bx - 26624) * 256 + tid;   // < 8*1024*512
        int qv = (int)(i >> 9), c = (int)(i & 511);
        float v = cb[(long long)qv * NC + c];
        __half h1, h2;
        split2h(v, h1, h2);
        long long o = (long long)qv * NC + gpos16(c);
        g_cbh[o]           = h1;
        g_cbh[o + CBPLANE] = h2;
    }
}

// ---------------- launch 1: fully fused s=1 quantize ----------------
__global__ __launch_bounds__(256) void quant_s1_kernel(const float* __restrict__ cb) {
    __shared__ float xs[512];
    __shared__ unsigned long long wbest[8];
    int b = blockIdx.x;
    int tid = threadIdx.x;
    int wp = tid >> 5, lane = tid & 31;

    for (int i = 0; i < 64; i++) {
        int row = wp * 64 + i;
        float4 v = ((const float4*)(g_zq + (long long)(b * NC + row) * NT))[lane];
        float s = v.x + v.y + v.z + v.w;
        for (int o = 16; o > 0; o >>= 1) s += __shfl_xor_sync(0xffffffffu, s, o);
        if (lane == 0) xs[row] = s * (1.0f / 128.0f);
    }
    __syncthreads();

    float bestv = INFINITY;
    int besti = 0;
    for (int cc = 0; cc < 128; cc++) {
        int code = wp * 128 + cc;
        const float* cbr = cb + (long long)code * 512;
        float d = 0.0f;
#pragma unroll
        for (int e = 0; e < 16; e++) d += xs[lane + 32 * e] * cbr[lane + 32 * e];
        for (int o = 16; o > 0; o >>= 1) d += __shfl_xor_sync(0xffffffffu, d, o);
        float sc = g_cnorm[code] - 2.0f * d;
        if (sc < bestv) { bestv = sc; besti = code; }
    }
    if (lane == 0) {
        unsigned u = __float_as_uint(bestv);
        u = (u & 0x80000000u) ? ~u : (u | 0x80000000u);
        wbest[wp] = ((unsigned long long)u << 32) | (unsigned)besti;
    }
    __syncthreads();
    if (tid == 0) {
        unsigned long long k = wbest[0];
        for (int i = 1; i < 8; i++) if (wbest[i] < k) k = wbest[i];
        int idx = (int)(k & 0xFFFFFFFFULL);
        g_idxbuf[b * NIDX] = idx;
        atomicAdd(&g_counts[idx], 1);
    }
}

// ---------------- downsample ----------------
__global__ void downsample_warp_kernel(int s, int slog) {
    int r = NT >> slog;
    int i = blockIdx.x * 8 + (threadIdx.x >> 5);
    int lane = threadIdx.x & 31;
    if (i >= NB * NC * s) return;
    int j  = i & (s - 1);
    int bc = i >> slog;
    const float* src = g_zq + (long long)bc * NT + j * r;
    float acc;
    if (r == 64) { float2 v = ((const float2*)src)[lane]; acc = v.x + v.y; }
    else         { acc = src[lane]; }
    for (int o = 16; o > 0; o >>= 1) acc += __shfl_xor_sync(0xffffffffu, acc, o);
    if (lane == 0) g_xd[i] = acc * (1.0f / (float)r);
}
__global__ void downsample_kernel(int s, int slog, int tohalf) {
    int total = NB * NC * s;
    int r = NT >> slog;
    int i = blockIdx.x * blockDim.x + threadIdx.x;
    if (i >= total) return;
    int j  = i & (s - 1);
    int bc = i >> slog;
    const float* src = g_zq + (long long)bc * NT + j * r;
    float acc = 0.0f;
    for (int k = 0; k < r; k++) acc += src[k];
    acc *= (1.0f / (float)r);
    if (!tohalf) {
        g_xd[i] = acc;
    } else {
        int b = bc >> 9, c = bc & 511;
        long long m = (long long)b * s + j;
        __half h1, h2;
        split2h(acc, h1, h2);
        long long o = m * 512 + gpos16(c);
        g_xdh[o]           = h1;
        g_xdh[o + XDPLANE] = h2;
    }
}

// ---------------- quantize (s in 2..8) ----------------
template<int S>
__global__ __launch_bounds__(256) void quantize_small_kernel(const float* __restrict__ cb, int q) {
    __shared__ float xs[S][512];
    int b  = blockIdx.x;
    int c0 = blockIdx.y * 128;
    int tid = threadIdx.x;
    for (int e = tid; e < S * 512; e += 256) {
        int j = e >> 9, ch = e & 511;
        xs[j][ch] = g_xd[(b * 512 + ch) * S + j];
    }
    __syncthreads();
    int w = tid >> 5, lane = tid & 31;
    float bestv[S]; int besti[S];
#pragma unroll
    for (int j = 0; j < S; j++) { bestv[j] = INFINITY; besti[j] = 0; }
    for (int cc = 0; cc < 16; cc++) {
        int code = c0 + w * 16 + cc;
        const float* cbr = cb + (long long)code * 512;
        float cv[16];
#pragma unroll
        for (int e = 0; e < 16; e++) cv[e] = cbr[lane + 32 * e];
        float cn = g_cnorm[q * NV + code];
#pragma unroll
        for (int j = 0; j < S; j++) {
            float d = 0.0f;
#pragma unroll
            for (int e = 0; e < 16; e++) d += xs[j][lane + 32 * e] * cv[e];
            for (int o = 16; o > 0; o >>= 1) d += __shfl_xor_sync(0xffffffffu, d, o);
            float sc = cn - 2.0f * d;
            if (sc < bestv[j]) { bestv[j] = sc; besti[j] = code; }
        }
    }
    if (lane == 0) {
#pragma unroll
        for (int j = 0; j < S; j++) {
            unsigned u = __float_as_uint(bestv[j]);
            u = (u & 0x80000000u) ? ~u : (u | 0x80000000u);
            atomicMin(&g_bestkey[b * S + j], ((unsigned long long)u << 32) | (unsigned)besti[j]);
        }
    }
}

// ---------------- quantize (s>=16): fp16 tensor-core GEMM + fused argmin ----------------
// grid (M/128, 8), block 256 (8 warps: 2m x 4n), warp tile m64 x n32. K=512 in 32 chunks of 16.
__global__ __launch_bounds__(256) void quantize_tc_kernel(
    const __half* __restrict__ xdh,  // [2][M][512] perm16
    const __half* __restrict__ cbh,  // [2-plane strided][1024][512] perm16 (this scale)
    int q)
{
    __shared__ __align__(16) char smq[32768];
    const unsigned sbase = smem_u32(smq);
    const int tid = threadIdx.x, lane = tid & 31, wid = tid >> 5;
    const int wm = wid >> 2, wn = wid & 3;
    const int lq = lane >> 2, lr = lane & 3;
    const int m0 = blockIdx.x * 128, n0 = blockIdx.y * 128;

    float acc[4][4][4];
#pragma unroll
    for (int mt = 0; mt < 4; mt++)
#pragma unroll
        for (int nt = 0; nt < 4; nt++)
#pragma unroll
            for (int r = 0; r < 4; r++) acc[mt][nt][r] = 0.0f;

    // hoisted cp.async addressing: A 512 quads, B 512 quads, 256 threads -> 2+2 each
    const char* asrc[2]; unsigned adst[2];
    const char* bsrc[2]; unsigned bdst[2];
#pragma unroll
    for (int i = 0; i < 2; i++) {
        int e = tid + 256 * i;
        int sp = e >> 8, r = e & 255, row = r >> 1, qq = r & 1;
        asrc[i] = (const char*)(xdh + (long long)sp * XDPLANE + (long long)(m0 + row) * 512) + qq * 16;
        adst[i] = sbase + (unsigned)(sp * 4096 + row * 32 + qq * 16);
        bsrc[i] = (const char*)(cbh + (long long)sp * CBPLANE + (long long)(n0 + row) * 512) + qq * 16;
        bdst[i] = sbase + (unsigned)(16384 + sp * 4096 + row * 32 + qq * 16);
    }
    int del = 8192;

#define QISSUE() do { \
    _Pragma("unroll") \
    for (int i = 0; i < 2; i++) { \
        asm volatile("cp.async.cg.shared.global [%0], [%1], 16;" :: "r"(adst[i]), "l"(asrc[i])); \
        asrc[i] += 32; adst[i] += del; \
        asm volatile("cp.async.cg.shared.global [%0], [%1], 16;" :: "r"(bdst[i]), "l"(bsrc[i])); \
        bsrc[i] += 32; bdst[i] += del; \
    } \
    del = -del; \
} while (0)

    QISSUE();
    asm volatile("cp.async.commit_group;");

    for (int ch = 0; ch < 32; ch++) {
        const int buf = ch & 1;
        asm volatile("cp.async.wait_group 0;");
        __syncthreads();
        if (ch < 31) QISSUE();
        asm volatile("cp.async.commit_group;");

        const char* Ahi = smq + buf * 8192;
        const char* Alo = Ahi + 4096;
        const char* Bhi = smq + 16384 + buf * 8192;
        const char* Blo = Bhi + 4096;

        uint2 bhi[4], blo[4];
#pragma unroll
        for (int nt = 0; nt < 4; nt++) {
            int brow = wn * 32 + nt * 8 + lq;
            bhi[nt] = *(const uint2*)(Bhi + brow * 32 + lr * 8);
            blo[nt] = *(const uint2*)(Blo + brow * 32 + lr * 8);
        }
        unsigned a[4][4];
#pragma unroll
        for (int mt = 0; mt < 4; mt++) {
            int arow = wm * 64 + mt * 16 + lq;
            uint2 p0 = *(const uint2*)(Ahi + arow * 32 + lr * 8);
            uint2 p1 = *(const uint2*)(Ahi + (arow + 8) * 32 + lr * 8);
            a[mt][0] = p0.x; a[mt][1] = p1.x; a[mt][2] = p0.y; a[mt][3] = p1.y;
        }
#pragma unroll
        for (int nt = 0; nt < 4; nt++)
#pragma unroll
            for (int mt = 0; mt < 4; mt++)
                mma_f16(acc[mt][nt], a[mt], bhi[nt]);
#pragma unroll
        for (int nt = 0; nt < 4; nt++)
#pragma unroll
            for (int mt = 0; mt < 4; mt++)
                mma_f16(acc[mt][nt], a[mt], blo[nt]);
#pragma unroll
        for (int mt = 0; mt < 4; mt++) {
            int arow = wm * 64 + mt * 16 + lq;
            uint2 p0 = *(const uint2*)(Alo + arow * 32 + lr * 8);
            uint2 p1 = *(const uint2*)(Alo + (arow + 8) * 32 + lr * 8);
            a[mt][0] = p0.x; a[mt][1] = p1.x; a[mt][2] = p0.y; a[mt][3] = p1.y;
        }
#pragma unroll
        for (int nt = 0; nt < 4; nt++)
#pragma unroll
            for (int mt = 0; mt < 4; mt++)
                mma_f16(acc[mt][nt], a[mt], bhi[nt]);
    }
#undef QISSUE

    // ---- scores + argmin ----
    float bv0[4], bv1[4]; int bi0[4], bi1[4];
#pragma unroll
    for (int mt = 0; mt < 4; mt++) { bv0[mt] = INFINITY; bv1[mt] = INFINITY; bi0[mt] = 0; bi1[mt] = 0; }
#pragma unroll
    for (int nt = 0; nt < 4; nt++) {
        int n = n0 + wn * 32 + nt * 8 + 2 * lr;
        float cn0 = g_cnorm[q * NV + n];
        float cn1 = g_cnorm[q * NV + n + 1];
#pragma unroll
        for (int mt = 0; mt < 4; mt++) {
            float s0 = cn0 - 2.0f * acc[mt][nt][0];
            float s1 = cn1 - 2.0f * acc[mt][nt][1];
            float s2 = cn0 - 2.0f * acc[mt][nt][2];
            float s3 = cn1 - 2.0f * acc[mt][nt][3];
            if (s0 < bv0[mt]) { bv0[mt] = s0; bi0[mt] = n; }
            if (s1 < bv0[mt]) { bv0[mt] = s1; bi0[mt] = n + 1; }
            if (s2 < bv1[mt]) { bv1[mt] = s2; bi1[mt] = n; }
            if (s3 < bv1[mt]) { bv1[mt] = s3; bi1[mt] = n + 1; }
        }
    }
#pragma unroll
    for (int mt = 0; mt < 4; mt++) {
        float v0 = bv0[mt], v1 = bv1[mt];
        int i0 = bi0[mt], i1 = bi1[mt];
#pragma unroll
        for (int off = 1; off <= 2; off <<= 1) {
            float ov = __shfl_xor_sync(0xffffffffu, v0, off);
            int   oi = __shfl_xor_sync(0xffffffffu, i0, off);
            if (ov < v0 || (ov == v0 && oi < i0)) { v0 = ov; i0 = oi; }
            ov = __shfl_xor_sync(0xffffffffu, v1, off);
            oi = __shfl_xor_sync(0xffffffffu, i1, off);
            if (ov < v1 || (ov == v1 && oi < i1)) { v1 = ov; i1 = oi; }
        }
        if (lr == 0) {
            int m = m0 + wm * 64 + mt * 16 + lq;
            unsigned u = __float_as_uint(v0);
            u = (u & 0x80000000u) ? ~u : (u | 0x80000000u);
            atomicMin(&g_bestkey[m], ((unsigned long long)u << 32) | (unsigned)i0);
            u = __float_as_uint(v1);
            u = (u & 0x80000000u) ? ~u : (u | 0x80000000u);
            atomicMin(&g_bestkey[m + 8], ((unsigned long long)u << 32) | (unsigned)i1);
        }
    }
}

// ---------------- extract idx + histogram (s>=2) ----------------
__global__ void post_quantize_kernel(int s, int slog) {
    int m = blockIdx.x * blockDim.x + threadIdx.x;
    if (m >= NB * s) return;
    int v = (int)(g_bestkey[m] & 0xFFFFFFFFULL);
    int b = m >> slog, j = m & (s - 1);
    g_idxbuf[b * NIDX + (s - 1) + j] = v;
    atomicAdd(&g_counts[v], 1);
}

// ---------------- upsample -> fp16 splits (ci perm16) ----------------
__global__ void upsample_split_kernel(const float* __restrict__ cb, int s) {
    int b = blockIdx.x, t = blockIdx.y;
    float u = (t + 0.5f) * ((float)s / 128.0f) - 0.5f;
    float jf = floorf(u);
    float f = u - jf;
    int j0 = (int)jf, j1 = j0 + 1;
    if (j0 < 0) j0 = 0; if (j0 > s - 1) j0 = s - 1;
    if (j1 < 0) j1 = 0; if (j1 > s - 1) j1 = s - 1;
    int v0 = g_idxbuf[b * NIDX + (s - 1) + j0];
    int v1 = g_idxbuf[b * NIDX + (s - 1) + j1];
    const float* c0 = cb + (long long)v0 * NC;
    const float* c1 = cb + (long long)v1 * NC;
    float w1 = f, w0 = 1.0f - f;
    long long base = ((long long)(b * NT + t)) * NC;
    for (int c = threadIdx.x; c < NC; c += 128) {
        float val = w0 * c0[c] + w1 * c1[c];
        __half h1, h2;
        split2h(val, h1, h2);
        int cp = gpos16(c);
        g_xs_a[base + cp]         = h1;
        g_xs_a[base + cp + PLANE] = h2;
    }
}

// ---------------- fp16 mma conv: m16n8k16, 16-ci chunks, 2-deep cp.async, hoisted addressing ----------------
#define WBUF_B 24576
#define XOFF_B 49152
#define XBUF_B 16640
#define CONV_SMEM (XOFF_B + 2*XBUF_B)
__global__ __launch_bounds__(512, 1) void conv_tc_kernel(
    const __half* __restrict__ xs,   // [2][b][t][ci-perm16]
    const __half* __restrict__ wsp,  // [6][co][ci-perm16] for this layer
    const float* __restrict__ bias,
    __half* __restrict__ ys,
    const float* __restrict__ z, int fuse)
{
    extern __shared__ char smc[];
    float* smf = (float*)smc;
    const unsigned sbase = smem_u32(smc);
    const int tid = threadIdx.x, lane = tid & 31, wid = tid >> 5;
    const int h = wid >> 3, wh = wid & 7;
    const int cg = wh >> 2, tg = wh & 3;
    const int b0 = blockIdx.y * 2, co0 = blockIdx.x * 128;
    const int lq = lane >> 2, lr = lane & 3;

    for (int e = tid; e < 128; e += 512) {
        int word = e & 7, row2 = (e >> 3) & 1, pl = (e >> 4) & 3, buf = e >> 6;
        *(unsigned*)(smc + XOFF_B + buf * XBUF_B + pl * 4160 + (row2 ? 129 : 0) * 32 + word * 4) = 0u;
    }

    float acc[4][4][4];
#pragma unroll
    for (int mt = 0; mt < 4; mt++)
#pragma unroll
        for (int nt = 0; nt < 4; nt++)
#pragma unroll
            for (int r = 0; r < 4; r++) acc[mt][nt][r] = 0.0f;

    const char* wsrc[3]; unsigned wdst[3];
#pragma unroll
    for (int i = 0; i < 3; i++) {
        int e = tid + 512 * i;
        int tile = e >> 8, r = e & 255, row = r >> 1, q = r & 1;
        wsrc[i] = (const char*)(wsp + (long long)tile * (NC * NC)
                                + (long long)(co0 + row) * NC) + q * 16;
        wdst[i] = sbase + (unsigned)(tile * 4096 + row * 32 + q * 16);
    }
    const char* xsrc[2]; unsigned xdst[2];
#pragma unroll
    for (int i = 0; i < 2; i++) {
        int e = tid + 512 * i;
        int hbsp = e >> 8, r = e & 255, row = r >> 1, q = r & 1;
        int hb = hbsp >> 1, sp = hbsp & 1;
        xsrc[i] = (const char*)(xs + (long long)sp * PLANE
                                + ((long long)((b0 + hb) * NT + row)) * NC) + q * 16;
        xdst[i] = sbase + (unsigned)(XOFF_B + hbsp * 4160 + (row + 1) * 32 + q * 16);
    }
    int wdel = WBUF_B, xdel = XBUF_B;

#define ISSUE_ALL() do { \
    _Pragma("unroll") \
    for (int i = 0; i < 3; i++) { \
        asm volatile("cp.async.cg.shared.global [%0], [%1], 16;" :: "r"(wdst[i]), "l"(wsrc[i])); \
        wsrc[i] += 32; wdst[i] += wdel; \
    } \
    _Pragma("unroll") \
    for (int i = 0; i < 2; i++) { \
        asm volatile("cp.async.cg.shared.global [%0], [%1], 16;" :: "r"(xdst[i]), "l"(xsrc[i])); \
        xsrc[i] += 32; xdst[i] += xdel; \
    } \
    wdel = -wdel; xdel = -xdel; \
} while (0)

    ISSUE_ALL();
    asm volatile("cp.async.commit_group;");

    for (int ch = 0; ch < 32; ch++) {
        const int buf = ch & 1;
        asm volatile("cp.async.wait_group 0;");
        __syncthreads();

        if (ch < 31) ISSUE_ALL();
        asm volatile("cp.async.commit_group;");

        const char* Wb = smc + buf * WBUF_B;
        const char* Xw = smc + XOFF_B + buf * XBUF_B + h * 8320;
#pragma unroll
        for (int tap = 0; tap < 3; tap++) {
            const char* Whi = Wb + tap * 4096;
            const char* Wlo = Wb + (3 + tap) * 4096;
            uint2 bhi[4], blo[4];
#pragma unroll
            for (int nt = 0; nt < 4; nt++) {
                int trow = tg * 32 + nt * 8 + lq + tap;
                bhi[nt] = *(const uint2*)(Xw + trow * 32 + lr * 8);
                blo[nt] = *(const uint2*)(Xw + 4160 + trow * 32 + lr * 8);
            }
            unsigned a[4][4];
#pragma unroll
            for (int mt = 0; mt < 4; mt++) {
                int row = cg * 64 + mt * 16 + lq;
                uint2 p0 = *(const uint2*)(Whi + row * 32 + lr * 8);
                uint2 p1 = *(const uint2*)(Whi + (row + 8) * 32 + lr * 8);
                a[mt][0] = p0.x; a[mt][1] = p1.x; a[mt][2] = p0.y; a[mt][3] = p1.y;
            }
#pragma unroll
            for (int nt = 0; nt < 4; nt++)
#pragma unroll
                for (int mt = 0; mt < 4; mt++)
                    mma_f16(acc[mt][nt], a[mt], bhi[nt]);
#pragma unroll
            for (int nt = 0; nt < 4; nt++)
#pragma unroll
                for (int mt = 0; mt < 4; mt++)
                    mma_f16(acc[mt][nt], a[mt], blo[nt]);
#pragma unroll
            for (int mt = 0; mt < 4; mt++) {
                int row = cg * 64 + mt * 16 + lq;
                uint2 p0 = *(const uint2*)(Wlo + row * 32 + lr * 8);
                uint2 p1 = *(const uint2*)(Wlo + (row + 8) * 32 + lr * 8);
                a[mt][0] = p0.x; a[mt][1] = p1.x; a[mt][2] = p0.y; a[mt][3] = p1.y;
            }
#pragma unroll
            for (int nt = 0; nt < 4; nt++)
#pragma unroll
                for (int mt = 0; mt < 4; mt++)
                    mma_f16(acc[mt][nt], a[mt], bhi[nt]);
        }
    }
#undef ISSUE_ALL

    if (!fuse) {
        for (int hb = 0; hb < 2; hb++) {
            __syncthreads();
            if (h == hb) {
#pragma unroll
                for (int mt = 0; mt < 4; mt++)
#pragma unroll
                    for (int nt = 0; nt < 4; nt++) {
                        int row = cg * 64 + mt * 16 + lq;
                        int t0 = tg * 32 + nt * 8 + lr * 2;
                        smf[t0 * 130 + row]           = acc[mt][nt][0];
                        smf[(t0 + 1) * 130 + row]     = acc[mt][nt][1];
                        smf[t0 * 130 + row + 8]       = acc[mt][nt][2];
                        smf[(t0 + 1) * 130 + row + 8] = acc[mt][nt][3];
                    }
            }
            __syncthreads();
            int b = b0 + hb;
            for (int e = tid; e < 16384; e += 512) {
                int t = e >> 7, co = e & 127;
                float v = fmaxf(smf[t * 130 + co] + bias[co0 + co], 0.0f);
                __half h1, h2;
                split2h(v, h1, h2);
                int c = co0 + co;
                long long o = ((long long)(b * NT + t)) * NC + gpos16(c);
                ys[o]         = h1;
                ys[o + PLANE] = h2;
            }
        }
    } else {
        float lsum = 0.0f;
        int b = b0 + h;
#pragma unroll
        for (int mt = 0; mt < 4; mt++)
#pragma unroll
            for (int nt = 0; nt < 4; nt++) {
                int row = cg * 64 + mt * 16 + lq;
                int t0 = tg * 32 + nt * 8 + lr * 2;
#pragma unroll
                for (int hh = 0; hh < 2; hh++) {
                    int co = co0 + row + hh * 8;
                    float bv = bias[co];
                    float y0 = fmaxf(acc[mt][nt][hh * 2 + 0] + bv, 0.0f);
                    float y1 = fmaxf(acc[mt][nt][hh * 2 + 1] + bv, 0.0f);
                    long long i = ((long long)(b * NC + co)) * NT + t0;
                    float2 zh  = *(float2*)&g_zhat[i];
                    float2 zz  = *(const float2*)&z[i];
                    float2 zqv = *(float2*)&g_zq[i];
                    zh.x += y0; zh.y += y1;
                    *(float2*)&g_zhat[i] = zh;
                    zqv.x -= y0; zqv.y -= y1;
                    *(float2*)&g_zq[i] = zqv;
                    float d0 = zh.x - zz.x, d1 = zh.y - zz.y;
                    lsum += d0 * d0 + d1 * d1;
                }
            }
        __syncthreads();
        for (int o = 16; o > 0; o >>= 1) lsum += __shfl_down_sync(0xffffffffu, lsum, o);
        if ((tid & 31) == 0) smf[tid >> 5] = lsum;
        __syncthreads();
        if (tid == 0) {
            float s = 0.0f;
#pragma unroll
            for (int i2 = 0; i2 < 16; i2++) s += smf[i2];
            g_partial[blockIdx.y * 4 + blockIdx.x] = s;
        }
    }
}

// ---------------- per-scale finalize ----------------
__global__ void finalize_kernel(int s) {
    __shared__ float sh[32];
    int tid = threadIdx.x;
    float lsum = (tid < 128) ? g_partial[tid] : 0.0f;
    for (int o = 16; o > 0; o >>= 1) lsum += __shfl_down_sync(0xffffffffu, lsum, o);
    if ((tid & 31) == 0) sh[tid >> 5] = lsum;
    __syncthreads();
    float loss_total = 0.0f;
    if (tid == 0) for (int w = 0; w < 32; w++) loss_total += sh[w];
    __syncthreads();
    int c = g_counts[tid];
    float used = (c > 0) ? 1.0f : 0.0f;
    float p = (float)c / (float)(NB * s);
    float ent = p * logf(p + 1e-10f);
    float us = used;
    for (int o = 16; o > 0; o >>= 1) us += __shfl_down_sync(0xffffffffu, us, o);
    if ((tid & 31) == 0) sh[tid >> 5] = us;
    __syncthreads();
    float used_total = 0.0f;
    if (tid == 0) for (int w = 0; w < 32; w++) used_total += sh[w];
    __syncthreads();
    float es = ent;
    for (int o = 16; o > 0; o >>= 1) es += __shfl_down_sync(0xffffffffu, es, o);
    if ((tid & 31) == 0) sh[tid >> 5] = es;
    __syncthreads();
    float ent_total = 0.0f;
    if (tid == 0) for (int w = 0; w < 32; w++) ent_total += sh[w];
    if (tid == 0) {
        g_sums[0] += used_total * (100.0f / (float)NV);
        g_sums[1] += 1.25f * loss_total / (float)NELEM;
        g_sums[2] += expf(-ent_total);
    }
    g_counts[tid] = 0;
    for (int i = tid; i < NB * NT; i += 1024) g_bestkey[i] = ~0ULL;
}

// ---------------- write outputs ----------------
__global__ void writeout_kernel(float* __restrict__ out, int out_size) {
    long long stride = (long long)gridDim.x * blockDim.x;
    long long t0 = (long long)blockIdx.x * blockDim.x + threadIdx.x;
    for (long long i = t0; i < NELEM && i < out_size; i += stride) out[i] = g_zhat[i];
    if (t0 == 0) {
        if (NELEM + 0 < out_size) out[NELEM + 0] = g_sums[0] / 8.0f;
        if (NELEM + 1 < out_size) out[NELEM + 1] = g_sums[1] / 8.0f;
        if (NELEM + 2 < out_size) out[NELEM + 2] = g_sums[2] / 8.0f;
    }
    if (t0 < NB * NIDX && NELEM + 3 + t0 < out_size)
        out[NELEM + 3 + t0] = (float)g_idxbuf[t0];
}

// ---------------- host ----------------
extern "C" void kernel_launch(void* const* d_in, const int* in_sizes, int n_in,
                              void* d_out, int out_size) {
    const float* z  = (const float*)d_in[0];
    const float* cb = (const float*)d_in[1];
    const float* pw = (const float*)d_in[2];
    const float* pb = (const float*)d_in[3];
    float* out = (float*)d_out;

    void *p_xa = 0, *p_xb = 0, *p_w = 0, *p_xdh = 0, *p_cbh = 0;
    cudaGetSymbolAddress(&p_xa,  g_xs_a);
    cudaGetSymbolAddress(&p_xb,  g_xs_b);
    cudaGetSymbolAddress(&p_w,   g_wsp);
    cudaGetSymbolAddress(&p_xdh, g_xdh);
    cudaGetSymbolAddress(&p_cbh, g_cbh);
    cudaFuncSetAttribute(conv_tc_kernel, cudaFuncAttributeMaxDynamicSharedMemorySize, CONV_SMEM);

    mega_init_kernel<<<43008, 256>>>(z, cb, pw);                   // user launch 0

    for (int q = 0; q < NQ; q++) {
        int s = 1 << q, slog = q, M = NB * s;
        const float* cbq = cb + (long long)q * NV * NC;

        if (s == 1) {
            quant_s1_kernel<<<64, 256>>>(cbq);                     // launch 1
        } else if (s <= 4) {
            downsample_warp_kernel<<<(NB * NC * s) / 8, 256>>>(s, slog);
            if (s == 2) quantize_small_kernel<2><<<dim3(64, 8), 256>>>(cbq, q);
            else        quantize_small_kernel<4><<<dim3(64, 8), 256>>>(cbq, q);
            post_quantize_kernel<<<(M + 255) / 256, 256>>>(s, slog);
        } else if (s == 8) {
            downsample_kernel<<<(NB * NC * s + 255) / 256, 256>>>(s, slog, 0);
            quantize_small_kernel<8><<<dim3(64, 8), 256>>>(cbq, q);
            post_quantize_kernel<<<(M + 255) / 256, 256>>>(s, slog);
        } else {
            downsample_kernel<<<(NB * NC * s + 255) / 256, 256>>>(s, slog, 1);
            quantize_tc_kernel<<<dim3(M / 128, 8), 256>>>(
                (const __half*)p_xdh, (const __half*)p_cbh + (long long)q * NV * NC, q);
            post_quantize_kernel<<<(M + 255) / 256, 256>>>(s, slog);
        }

        upsample_split_kernel<<<dim3(NB, NT), 128>>>(cbq, s);      // q=0: launch 2

        const __half* w0 = (const __half*)p_w + ((long long)q * 2 + 0) * 6 * NC * NC;
        const __half* w1 = (const __half*)p_w + ((long long)q * 2 + 1) * 6 * NC * NC;
        const float* b0 = pb + ((long long)q * 2 + 0) * NC;
        const float* b1 = pb + ((long long)q * 2 + 1) * NC;
        conv_tc_kernel<<<dim3(4, 32), 512, CONV_SMEM>>>(
            (const __half*)p_xa, w0, b0, (__half*)p_xb, z, 0);     // q=0: launch 3 <-- ncu -s 5
        conv_tc_kernel<<<dim3(4, 32), 512, CONV_SMEM>>>(
            (const __half*)p_xb, w1, b1, (__half*)0, z, 1);

        finalize_kernel<<<1, 1024>>>(s);
    }

    writeout_kernel<<<2048, 256>>>(out, out_size);
}